// round 7
// baseline (speedup 1.0000x reference)
#include <cuda_runtime.h>
#include <cuda_bf16.h>
#include <cstdint>

// ---------------- problem constants ----------------
#define B_   8
#define K_   288
#define L_   16384
#define O_   64
#define NT   256
#define LT   256         // l-tile per CTA
#define CH   16          // k per chunk = one k-step
#define NCH  18
#define NKS  18
#define NSTG 4

// staging: [k=16][l=256 fp32 padded to 260] per stage
#define LSTR 260
#define STAGE_F (CH * LSTR)                 // 4160 floats
// output staging (aliases stage memory after drain): [l=256][o=64 pad 68]
#define SO_LD 68
#define SOUT_BYTES (LT * SO_LD * 4)         // 69632
#define STG_BYTES  (NSTG * STAGE_F * 4)     // 66560
#define SMEM_BYTES 69632                     // max of the two

// ---------------- prep outputs ----------------
__device__ uint2  g_wfrag[NKS * 8 * 32];    // B fragments [ks][nt][lane]
__device__ float4 g_wb4[O_ / 2];            // (w2,bias) pairs

__global__ void gauss_prep_kernel(const float* __restrict__ w,
                                  const float* __restrict__ bias) {
    int t = threadIdx.x;
    if (blockIdx.x < NKS) {
        int ks   = blockIdx.x;
        int nt   = t >> 5;
        int lane = t & 31;
        int k = ks * 16 + (lane & 3) * 2;
        int o = nt * 8 + (lane >> 2);
        __nv_bfloat162 b0 = __floats2bfloat162_rn(w[k * O_ + o], w[(k + 1) * O_ + o]);
        __nv_bfloat162 b1 = __floats2bfloat162_rn(w[(k + 8) * O_ + o], w[(k + 9) * O_ + o]);
        uint2 v;
        v.x = *reinterpret_cast<uint32_t*>(&b0);
        v.y = *reinterpret_cast<uint32_t*>(&b1);
        g_wfrag[(ks * 8 + nt) * 32 + lane] = v;
    } else {
        __shared__ float s_w2[O_];
        int o   = t >> 2;
        int sub = t & 3;
        float s = 0.f;
        #pragma unroll 8
        for (int k = sub; k < K_; k += 4) { float v = w[k * O_ + o]; s = fmaf(v, v, s); }
        s += __shfl_xor_sync(0xFFFFFFFF, s, 1);
        s += __shfl_xor_sync(0xFFFFFFFF, s, 2);
        if (sub == 0) s_w2[o] = s;
        __syncthreads();
        if (t < O_ / 2) {
            float4 r;
            r.x = s_w2[2 * t];     r.y = bias[2 * t];
            r.z = s_w2[2 * t + 1]; r.w = bias[2 * t + 1];
            g_wb4[t] = r;
        }
    }
}

// ---------------- PTX helpers ----------------
__device__ __forceinline__ void cp_async16(void* smem_dst, const void* gmem_src) {
    unsigned s = (unsigned)__cvta_generic_to_shared(smem_dst);
    asm volatile("cp.async.cg.shared.global [%0], [%1], 16;\n"
                 :: "r"(s), "l"(gmem_src) : "memory");
}
__device__ __forceinline__ void cp_commit() {
    asm volatile("cp.async.commit_group;\n" ::: "memory");
}
template<int N> __device__ __forceinline__ void cp_wait() {
    asm volatile("cp.async.wait_group %0;\n" :: "n"(N) : "memory");
}
__device__ __forceinline__ uint32_t packbf(float lo, float hi) {
    __nv_bfloat162 h = __floats2bfloat162_rn(lo, hi);
    return *reinterpret_cast<uint32_t*>(&h);
}
__device__ __forceinline__ void mma16816(float* c,
                                         uint32_t a0, uint32_t a1, uint32_t a2, uint32_t a3,
                                         uint32_t b0, uint32_t b1) {
    asm volatile(
        "mma.sync.aligned.m16n8k16.row.col.f32.bf16.bf16.f32 "
        "{%0,%1,%2,%3}, {%4,%5,%6,%7}, {%8,%9}, {%0,%1,%2,%3};"
        : "+f"(c[0]), "+f"(c[1]), "+f"(c[2]), "+f"(c[3])
        : "r"(a0), "r"(a1), "r"(a2), "r"(a3), "r"(b0), "r"(b1));
}

extern __shared__ float g_stg[];

// cooperative staging: warp w loads k-rows {2w, 2w+1}, each as 2 x 512B
// contiguous LDGSTS (full 1 KB row back-to-back).
__device__ __forceinline__ void issue_chunk(const float* __restrict__ xb,
                                            int c, int warp, int lane) {
    float* dst = g_stg + (c & (NSTG - 1)) * STAGE_F;
    #pragma unroll
    for (int r = 0; r < 2; ++r) {
        int kr = warp * 2 + r;
        const float* src = xb + (size_t)(c * CH + kr) * L_;
        float* d = dst + kr * LSTR;
        #pragma unroll
        for (int j = 0; j < 2; ++j)
            cp_async16(d + j * 128 + lane * 4, src + j * 128 + lane * 4);
    }
}

__global__ __launch_bounds__(NT, 2)
void gauss_main_kernel(const float* __restrict__ x,
                       const float* __restrict__ gamma_p,
                       float* __restrict__ out) {
    const int t    = threadIdx.x;
    const int warp = t >> 5;
    const int lane = t & 31;
    const int bx   = blockIdx.x;
    const int b    = bx >> 6;              // 64 l-tiles per batch
    const int l0   = (bx & 63) * LT;

    const float* xb = x + (size_t)b * K_ * L_ + l0;

    const int kc  = (lane & 3) * 2;
    const int llo = lane >> 2;
    const int lw  = warp * 32;             // warp's l offset within tile

    float acc[2][8][4];
    #pragma unroll
    for (int s = 0; s < 2; ++s)
        #pragma unroll
        for (int i = 0; i < 8; ++i)
            #pragma unroll
            for (int j = 0; j < 4; ++j) acc[s][i][j] = 0.f;
    float x2a[2][2] = {{0.f, 0.f}, {0.f, 0.f}};

    // prologue: 3 chunks in flight
    #pragma unroll
    for (int p = 0; p < NSTG - 1; ++p) { issue_chunk(xb, p, warp, lane); cp_commit(); }

    // ---------------- mainloop, 1 barrier per chunk ----------------
    #pragma unroll 1
    for (int c = 0; c < NCH; ++c) {
        cp_wait<NSTG - 2>();               // own copies of chunk c done
        __syncthreads();                   // all warps' copies visible; c-1 consumed

        if (c + NSTG - 1 < NCH) issue_chunk(xb, c + NSTG - 1, warp, lane);
        cp_commit();

        const float* st = g_stg + (c & (NSTG - 1)) * STAGE_F;
        const uint2* wf = g_wfrag + (c * 8) * 32 + lane;

        #pragma unroll
        for (int s = 0; s < 2; ++s) {
            const float* p0 = st + lw + s * 16 + llo;
            float vl0 = p0[(kc + 0) * LSTR];
            float vl1 = p0[(kc + 1) * LSTR];
            float vl8 = p0[(kc + 8) * LSTR];
            float vl9 = p0[(kc + 9) * LSTR];
            float vh0 = p0[(kc + 0) * LSTR + 8];
            float vh1 = p0[(kc + 1) * LSTR + 8];
            float vh8 = p0[(kc + 8) * LSTR + 8];
            float vh9 = p0[(kc + 9) * LSTR + 8];

            x2a[s][0] = fmaf(vl0, vl0, x2a[s][0]); x2a[s][0] = fmaf(vl1, vl1, x2a[s][0]);
            x2a[s][0] = fmaf(vl8, vl8, x2a[s][0]); x2a[s][0] = fmaf(vl9, vl9, x2a[s][0]);
            x2a[s][1] = fmaf(vh0, vh0, x2a[s][1]); x2a[s][1] = fmaf(vh1, vh1, x2a[s][1]);
            x2a[s][1] = fmaf(vh8, vh8, x2a[s][1]); x2a[s][1] = fmaf(vh9, vh9, x2a[s][1]);

            uint32_t A0 = packbf(vl0, vl1);
            uint32_t A1 = packbf(vh0, vh1);
            uint32_t A2 = packbf(vl8, vl9);
            uint32_t A3 = packbf(vh8, vh9);

            #pragma unroll
            for (int nt = 0; nt < 8; ++nt) {
                uint2 bb = wf[nt * 32];    // L1-resident
                mma16816(acc[s][nt], A0, A1, A2, A3, bb.x, bb.y);
            }
        }
    }

    // x2 reduction across the 4 lanes sharing each l row
    #pragma unroll
    for (int s = 0; s < 2; ++s)
        #pragma unroll
        for (int hh = 0; hh < 2; ++hh) {
            x2a[s][hh] += __shfl_xor_sync(0xFFFFFFFF, x2a[s][hh], 1);
            x2a[s][hh] += __shfl_xor_sync(0xFFFFFFFF, x2a[s][hh], 2);
        }

    // ---------------- epilogue: exp into smem, then coalesced stores --------
    cp_wait<0>();
    __syncthreads();                       // stages fully drained & consumed
    float* sOut = g_stg;                   // [LT][SO_LD] aliases staging

    const float gamma = __ldg(gamma_p);
    #pragma unroll
    for (int s = 0; s < 2; ++s) {
        float* so = sOut + (size_t)(lw + s * 16) * SO_LD;
        #pragma unroll
        for (int nt = 0; nt < 8; ++nt) {
            const int o = nt * 8 + kc;
            float4 wb = g_wb4[nt * 4 + (lane & 3)];
            float2 r0, r1;
            r0.x = __expf(-gamma * (x2a[s][0] + wb.x - 2.f * acc[s][nt][0])) + wb.y;
            r0.y = __expf(-gamma * (x2a[s][0] + wb.z - 2.f * acc[s][nt][1])) + wb.w;
            r1.x = __expf(-gamma * (x2a[s][1] + wb.x - 2.f * acc[s][nt][2])) + wb.y;
            r1.y = __expf(-gamma * (x2a[s][1] + wb.z - 2.f * acc[s][nt][3])) + wb.w;
            *reinterpret_cast<float2*>(so + (size_t)llo * SO_LD + o)       = r0;
            *reinterpret_cast<float2*>(so + (size_t)(llo + 8) * SO_LD + o) = r1;
        }
    }
    __syncthreads();

    // flat copy: CTA's output region is 64 KB contiguous in gmem
    float* ob = out + ((size_t)b * L_ + l0) * O_;
    #pragma unroll
    for (int i = t; i < LT * (O_ / 4); i += NT) {   // 4096 float4s, 16 iters
        const int row = i >> 4;
        const int col = (i & 15) << 2;
        float4 v = *reinterpret_cast<const float4*>(sOut + (size_t)row * SO_LD + col);
        *reinterpret_cast<float4*>(ob + (size_t)row * O_ + col) = v;
    }
}

extern "C" void kernel_launch(void* const* d_in, const int* in_sizes, int n_in,
                              void* d_out, int out_size) {
    const float* x     = (const float*)d_in[0];
    const float* w     = (const float*)d_in[1];
    const float* bias  = (const float*)d_in[2];
    const float* gamma = (const float*)d_in[3];
    float* out = (float*)d_out;

    cudaFuncSetAttribute(gauss_main_kernel,
                         cudaFuncAttributeMaxDynamicSharedMemorySize, SMEM_BYTES);

    gauss_prep_kernel<<<NKS + 1, NT>>>(w, bias);
    gauss_main_kernel<<<B_ * (L_ / LT), NT, SMEM_BYTES>>>(x, gamma, out);
    (void)in_sizes; (void)n_in; (void)out_size;
}